// round 5
// baseline (speedup 1.0000x reference)
#include <cuda_runtime.h>
#include <cuda_bf16.h>
#include <math.h>
#include <stdint.h>

// Problem constants
#define BATCH 8
#define CIN   256
#define COUT  256
#define H     64
#define W     64
#define H2    128
#define W2    128
#define KTAP  9
#define Y_ELEMS (BATCH*COUT*H*W)          // 8388608

// Scratch (device globals — no cudaMalloc allowed)
__device__ float g_offmask[BATCH * 27 * H * W];       // 3.5 MB
// Deconv A in per-thread MMA fragment order (tf32 bits), M=256:
// [cls(4)][ks(128)][m16t(16)][lane(32)][frag(4)]  = 4 MB
__device__ uint32_t g_wA[4 * 128 * 16 * 32 * 4];
// Deform A in per-thread MMA fragment order (tf32 bits), M=256:
// [ks(288)][m16t(16)][lane(32)][frag(4)]  = 2.36 MB
__device__ uint32_t g_wD[288 * 16 * 32 * 4];

// ---------------------------------------------------------------------------
// MMA helpers (sm_80 baseline PTX — legal on plain sm_103 target)
// ---------------------------------------------------------------------------
__device__ __forceinline__ uint32_t f2tf32(float v) {
    uint32_t u;
    asm("cvt.rna.tf32.f32 %0, %1;" : "=r"(u) : "f"(v));
    return u;
}
__device__ __forceinline__ void mma_tf32(float& d0, float& d1, float& d2, float& d3,
                                         uint32_t a0, uint32_t a1, uint32_t a2, uint32_t a3,
                                         uint32_t b0, uint32_t b1) {
    asm volatile("mma.sync.aligned.m16n8k8.row.col.f32.tf32.tf32.f32 "
                 "{%0,%1,%2,%3}, {%4,%5,%6,%7}, {%8,%9}, {%0,%1,%2,%3};"
                 : "+f"(d0), "+f"(d1), "+f"(d2), "+f"(d3)
                 : "r"(a0), "r"(a1), "r"(a2), "r"(a3), "r"(b0), "r"(b1));
}

// ---------------------------------------------------------------------------
// Kernel 0b: bake deconv A (M=256) into per-thread tf32 fragment order.
// kk = c*4 + s*2 + t;  A[o][kk] = w_up[c][o][3-(a+2s)][3-(qb+2t)]
// ---------------------------------------------------------------------------
__global__ void k_prep_wA(const float* __restrict__ w_up) {
    int e = blockIdx.x * 256 + threadIdx.x;   // 1,048,576 total
    int frag = e & 3;
    int lane = (e >> 2) & 31;
    int m16t = (e >> 7) & 15;
    int ks   = (e >> 11) & 127;
    int cls  = e >> 18;
    int a = cls >> 1, qb = cls & 1;
    int g = lane >> 2, tg = lane & 3;
    int o = m16t * 16 + g + 8 * (frag & 1);
    int kcol = tg + 4 * (frag >> 1);
    int kk = ks * 8 + kcol;
    int c = kk >> 2, s = (kk >> 1) & 1, t = kk & 1;
    float val = w_up[((c << 8) + o) * 16 + (3 - (a + 2 * s)) * 4 + (3 - (qb + 2 * t))];
    g_wA[e] = f2tf32(val);
}

// ---------------------------------------------------------------------------
// Kernel 0c: bake deform A (w_dcn, M=256) into per-thread tf32 fragment order.
// kk = c*9 + k  (K = 2304 = 288 ksteps of 8)
// ---------------------------------------------------------------------------
__global__ void k_prep_wD(const float* __restrict__ w_dcn) {
    int e = blockIdx.x * 256 + threadIdx.x;   // 589,824 total
    if (e >= 288 * 16 * 32 * 4) return;
    int frag = e & 3;
    int lane = (e >> 2) & 31;
    int m16t = (e >> 7) & 15;
    int ks   = e >> 11;                  // 0..287
    int g = lane >> 2, tg = lane & 3;
    int o = m16t * 16 + g + 8 * (frag & 1);
    int kcol = tg + 4 * (frag >> 1);
    int kk = ks * 8 + kcol;              // 0..2303
    int c = kk / 9;
    int k = kk - c * 9;
    g_wD[e] = f2tf32(w_dcn[(o * 256 + c) * 9 + k]);
}

// ---------------------------------------------------------------------------
// Kernel 1: 3x3 conv x * w_off + b_off -> g_offmask
// ---------------------------------------------------------------------------
__global__ void __launch_bounds__(256) k_off(const float* __restrict__ x,
                                             const float* __restrict__ w_off,
                                             const float* __restrict__ b_off) {
    __shared__ float xs[6][66];
    __shared__ float ws[9 * 28];

    int tid = threadIdx.x;
    int bidx = blockIdx.x;
    int b = bidx >> 4;
    int h0 = (bidx & 15) * 4;
    int r = tid >> 6;
    int wc = tid & 63;

    float acc[28];
#pragma unroll
    for (int i = 0; i < 28; i++) acc[i] = (i < 27) ? b_off[i] : 0.f;

    for (int c = 0; c < CIN; c++) {
        __syncthreads();
        if (tid < 243) {
            int co = tid / 9, kk = tid - co * 9;
            ws[kk * 28 + co] = w_off[co * (CIN * 9) + c * 9 + kk];
        }
        const float* xp = x + ((b * CIN + c) << 12);
        for (int i = tid; i < 396; i += 256) {
            int rr = i / 66, col = i - rr * 66;
            int hh = h0 - 1 + rr, ww = col - 1;
            float v = 0.f;
            if (hh >= 0 && hh < H && ww >= 0 && ww < W) v = xp[(hh << 6) + ww];
            xs[rr][col] = v;
        }
        __syncthreads();
#pragma unroll
        for (int kh = 0; kh < 3; kh++)
#pragma unroll
            for (int kw = 0; kw < 3; kw++) {
                float xv = xs[r + kh][wc + kw];
                const float4* w4 = (const float4*)&ws[(kh * 3 + kw) * 28];
#pragma unroll
                for (int q = 0; q < 7; q++) {
                    float4 wv = w4[q];
                    acc[q * 4 + 0] += xv * wv.x;
                    acc[q * 4 + 1] += xv * wv.y;
                    acc[q * 4 + 2] += xv * wv.z;
                    acc[q * 4 + 3] += xv * wv.w;
                }
            }
    }
    int h = h0 + r;
#pragma unroll
    for (int co = 0; co < 27; co++)
        g_offmask[((b * 27 + co) << 12) + (h << 6) + wc] = acc[co];
}

// ---------------------------------------------------------------------------
// Kernel 2: deformable conv via mma.sync tf32 GEMM + BN1 + ReLU.
// Grid 512: [b(8)][row(64)].  CTA: M=256 (all o), N=64 pixels (one h-row),
// K=2304, chunk=16.  8 warps = 4(M) x 2(N); warp tile 64x32.
// ---------------------------------------------------------------------------
__global__ void __launch_bounds__(256) k_deform_mma(const float* __restrict__ x,
                                                    const float* __restrict__ g1,
                                                    const float* __restrict__ be1,
                                                    const float* __restrict__ m1,
                                                    const float* __restrict__ v1,
                                                    float* __restrict__ yout) {
    __shared__ ushort4 s_idx[576];      // [pix(64)][tap(9)]
    __shared__ float4  s_wgt[576];
    __shared__ uint32_t Bs[2][64 * 20];

    int tid = threadIdx.x;
    int wid = tid >> 5, lane = tid & 31;
    int g = lane >> 2, tg = lane & 3;
    int warpM = wid >> 1, warpN = wid & 1;

    int bidx = blockIdx.x;
    int hrow = bidx & 63;
    int b = bidx >> 6;
    int pix0 = hrow << 6;

    // ---- Phase A: tap table (64 px x 9 taps) ----
    for (int e = tid; e < 576; e += 256) {
        int pix = e / 9, tap = e - pix * 9;
        int h = hrow, w = pix;
        const float* om = g_offmask + (b * 27) * 4096 + (h << 6) + w;
        float dy = om[tap * 4096];
        float dx = om[(9 + tap) * 4096];
        float ms = om[(18 + tap) * 4096];
        float m = 1.f / (1.f + expf(-ms));
        float py = dy + (float)(tap / 3 - 1 + h);
        float px = dx + (float)(tap % 3 - 1 + w);
        float fy = floorf(py), fx = floorf(px);
        float wy = py - fy, wx = px - fx;
        int y0 = (int)fy, x0 = (int)fx;
        int y1 = y0 + 1, x1 = x0 + 1;
        float vy0 = (y0 >= 0 && y0 < H) ? 1.f : 0.f;
        float vy1 = (y1 >= 0 && y1 < H) ? 1.f : 0.f;
        float vx0 = (x0 >= 0 && x0 < W) ? 1.f : 0.f;
        float vx1 = (x1 >= 0 && x1 < W) ? 1.f : 0.f;
        int cy0 = min(max(y0, 0), H - 1), cy1 = min(max(y1, 0), H - 1);
        int cx0 = min(max(x0, 0), W - 1), cx1 = min(max(x1, 0), W - 1);
        ushort4 id;
        id.x = (unsigned short)((cy0 << 6) + cx0);
        id.y = (unsigned short)((cy0 << 6) + cx1);
        id.z = (unsigned short)((cy1 << 6) + cx0);
        id.w = (unsigned short)((cy1 << 6) + cx1);
        s_idx[e] = id;
        float4 wv;
        wv.x = (1.f - wy) * (1.f - wx) * m * vy0 * vx0;
        wv.y = (1.f - wy) * wx * m * vy0 * vx1;
        wv.z = wy * (1.f - wx) * m * vy1 * vx0;
        wv.w = wy * wx * m * vy1 * vx1;
        s_wgt[e] = wv;
    }
    __syncthreads();

    // ---- B fill mapping: 16 kl x 16 nb, 4 pixels each ----
    int kl = tid & 15;
    int nb = tid >> 4;
    int n0 = nb << 2;
    const float* xb = x + (b << 20);

    float acc[4][4][4];
#pragma unroll
    for (int i = 0; i < 4; i++)
#pragma unroll
        for (int j = 0; j < 4; j++)
#pragma unroll
            for (int f = 0; f < 4; f++) acc[i][j][f] = 0.f;

    // fill chunk 0
    {
        int kk = kl;
        int c = kk / 9, tap = kk - c * 9;
        const float* xp = xb + (c << 12);
#pragma unroll
        for (int j = 0; j < 4; j++) {
            int e = (n0 + j) * 9 + tap;
            ushort4 id = s_idx[e];
            float4 wv = s_wgt[e];
            float v = wv.x * __ldg(xp + id.x) + wv.y * __ldg(xp + id.y) +
                      wv.z * __ldg(xp + id.z) + wv.w * __ldg(xp + id.w);
            Bs[0][(n0 + j) * 20 + kl] = f2tf32(v);
        }
    }
    __syncthreads();

    for (int chunk = 0; chunk < 144; chunk++) {
        int cur = chunk & 1;
        // prefetch next chunk's gathered values
        float pv[4];
        if (chunk < 143) {
            int kk = (chunk + 1) * 16 + kl;
            int c = kk / 9, tap = kk - c * 9;
            const float* xp = xb + (c << 12);
#pragma unroll
            for (int j = 0; j < 4; j++) {
                int e = (n0 + j) * 9 + tap;
                ushort4 id = s_idx[e];
                float4 wv = s_wgt[e];
                pv[j] = wv.x * __ldg(xp + id.x) + wv.y * __ldg(xp + id.y) +
                        wv.z * __ldg(xp + id.z) + wv.w * __ldg(xp + id.w);
            }
        }
        // MMA over 2 ksteps
#pragma unroll
        for (int ksv = 0; ksv < 2; ksv++) {
            uint32_t af[4][4];
#pragma unroll
            for (int mtl = 0; mtl < 4; mtl++) {
                uint4 q = *(const uint4*)(g_wD +
                    ((((chunk * 2 + ksv) * 16) + warpM * 4 + mtl) * 32 + lane) * 4);
                af[mtl][0] = q.x; af[mtl][1] = q.y; af[mtl][2] = q.z; af[mtl][3] = q.w;
            }
            uint32_t bf[4][2];
#pragma unroll
            for (int nt = 0; nt < 4; nt++) {
                int nrow = warpN * 32 + nt * 8 + g;
                bf[nt][0] = Bs[cur][nrow * 20 + ksv * 8 + tg];
                bf[nt][1] = Bs[cur][nrow * 20 + ksv * 8 + tg + 4];
            }
#pragma unroll
            for (int mtl = 0; mtl < 4; mtl++)
#pragma unroll
                for (int nt = 0; nt < 4; nt++)
                    mma_tf32(acc[mtl][nt][0], acc[mtl][nt][1], acc[mtl][nt][2], acc[mtl][nt][3],
                             af[mtl][0], af[mtl][1], af[mtl][2], af[mtl][3],
                             bf[nt][0], bf[nt][1]);
        }
        if (chunk < 143) {
            int nxt = cur ^ 1;
#pragma unroll
            for (int j = 0; j < 4; j++)
                Bs[nxt][(n0 + j) * 20 + kl] = f2tf32(pv[j]);
        }
        __syncthreads();
    }

    // ---- epilogue: BN1 + ReLU ----
#pragma unroll
    for (int mtl = 0; mtl < 4; mtl++)
#pragma unroll
        for (int hh = 0; hh < 2; hh++) {
            int o = warpM * 64 + mtl * 16 + g + hh * 8;
            float s_ = __ldg(g1 + o) * rsqrtf(__ldg(v1 + o) + 1e-5f);
            float sh = __ldg(be1 + o) - __ldg(m1 + o) * s_;
            float* ob = yout + (((b << 8) + o) << 12) + pix0;
#pragma unroll
            for (int nt = 0; nt < 4; nt++)
#pragma unroll
                for (int cc = 0; cc < 2; cc++) {
                    int n = warpN * 32 + nt * 8 + 2 * tg + cc;
                    float v = acc[mtl][nt][hh * 2 + cc];
                    ob[n] = fmaxf(fmaf(v, s_, sh), 0.f);
                }
        }
}

// ---------------------------------------------------------------------------
// Kernel 3: transposed conv via mma.sync tf32 GEMM + BN2 + ReLU.
// Grid 2048: [cls(4)][b(8)][pp(64)].  CTA: M=256, N=64 (one pp-row),
// K=1024, chunk=16.  8 warps = 4(M) x 2(N); warp tile 64x32.
// ---------------------------------------------------------------------------
__global__ void __launch_bounds__(256) k_deconv_mma(const float* __restrict__ y,
                                                    const float* __restrict__ g2,
                                                    const float* __restrict__ be2,
                                                    const float* __restrict__ m2,
                                                    const float* __restrict__ v2,
                                                    float* __restrict__ up) {
    __shared__ uint32_t Bs[2][64 * 20];

    int tid = threadIdx.x;
    int wid = tid >> 5, lane = tid & 31;
    int g = lane >> 2, tg = lane & 3;
    int warpM = wid >> 1, warpN = wid & 1;

    int bidx = blockIdx.x;
    int pp  = bidx & 63;
    int b   = (bidx >> 6) & 7;
    int cls = bidx >> 9;
    int a = cls >> 1, qb = cls & 1;

    int kl = tid & 15;
    int nb = tid >> 4;
    int c_l = kl >> 2, s = (kl >> 1) & 1, t = kl & 1;
    int qq0 = nb << 2;
    int n0 = qq0;
    int iy = pp + s + a - 1;
    bool rowok = (iy >= 0 && iy < H);
    const float* ybase = y + ((b << 8) << 12) + (iy << 6);
    int ix0 = qq0 + qb - 1 + t;

    float acc[4][4][4];
#pragma unroll
    for (int i = 0; i < 4; i++)
#pragma unroll
        for (int j = 0; j < 4; j++)
#pragma unroll
            for (int f = 0; f < 4; f++) acc[i][j][f] = 0.f;

    {
        const float* yr = ybase + (c_l << 12);
#pragma unroll
        for (int j = 0; j < 4; j++) {
            int ix = ix0 + j;
            float v = (rowok && ix >= 0 && ix < W) ? __ldg(yr + ix) : 0.f;
            Bs[0][(n0 + j) * 20 + kl] = f2tf32(v);
        }
    }
    __syncthreads();

    const uint32_t* Afrag = g_wA + cls * (128 * 16 * 32 * 4);

    for (int chunk = 0; chunk < 64; chunk++) {
        int cur = chunk & 1;
        float pv[4];
        if (chunk < 63) {
            const float* yr = ybase + (((chunk + 1) * 4 + c_l) << 12);
#pragma unroll
            for (int j = 0; j < 4; j++) {
                int ix = ix0 + j;
                pv[j] = (rowok && ix >= 0 && ix < W) ? __ldg(yr + ix) : 0.f;
            }
        }
#pragma unroll
        for (int ksv = 0; ksv < 2; ksv++) {
            uint32_t af[4][4];
#pragma unroll
            for (int mtl = 0; mtl < 4; mtl++) {
                uint4 q = *(const uint4*)(Afrag +
                    ((((chunk * 2 + ksv) * 16) + warpM * 4 + mtl) * 32 + lane) * 4);
                af[mtl][0] = q.x; af[mtl][1] = q.y; af[mtl][2] = q.z; af[mtl][3] = q.w;
            }
            uint32_t bf[4][2];
#pragma unroll
            for (int nt = 0; nt < 4; nt++) {
                int nrow = warpN * 32 + nt * 8 + g;
                bf[nt][0] = Bs[cur][nrow * 20 + ksv * 8 + tg];
                bf[nt][1] = Bs[cur][nrow * 20 + ksv * 8 + tg + 4];
            }
#pragma unroll
            for (int mtl = 0; mtl < 4; mtl++)
#pragma unroll
                for (int nt = 0; nt < 4; nt++)
                    mma_tf32(acc[mtl][nt][0], acc[mtl][nt][1], acc[mtl][nt][2], acc[mtl][nt][3],
                             af[mtl][0], af[mtl][1], af[mtl][2], af[mtl][3],
                             bf[nt][0], bf[nt][1]);
        }
        if (chunk < 63) {
            int nxt = cur ^ 1;
#pragma unroll
            for (int j = 0; j < 4; j++)
                Bs[nxt][(n0 + j) * 20 + kl] = f2tf32(pv[j]);
        }
        __syncthreads();
    }

    // ---- epilogue: BN2 + ReLU ----
    int p = (pp << 1) + a;
#pragma unroll
    for (int mtl = 0; mtl < 4; mtl++)
#pragma unroll
        for (int hh = 0; hh < 2; hh++) {
            int o = warpM * 64 + mtl * 16 + g + hh * 8;
            float s_ = __ldg(g2 + o) * rsqrtf(__ldg(v2 + o) + 1e-5f);
            float sh = __ldg(be2 + o) - __ldg(m2 + o) * s_;
            float* ob = up + (((b << 8) + o) << 14) + (p << 7) + qb;
#pragma unroll
            for (int nt = 0; nt < 4; nt++)
#pragma unroll
                for (int cc = 0; cc < 2; cc++) {
                    int qq = warpN * 32 + nt * 8 + 2 * tg + cc;
                    float v = acc[mtl][nt][hh * 2 + cc];
                    ob[qq << 1] = fmaxf(fmaf(v, s_, sh), 0.f);
                }
        }
}

// ---------------------------------------------------------------------------
extern "C" void kernel_launch(void* const* d_in, const int* in_sizes, int n_in,
                              void* d_out, int out_size) {
    const float* x      = (const float*)d_in[0];
    const float* w_off  = (const float*)d_in[1];
    const float* b_off  = (const float*)d_in[2];
    const float* w_dcn  = (const float*)d_in[3];
    const float* gamma1 = (const float*)d_in[4];
    const float* beta1  = (const float*)d_in[5];
    const float* mean1  = (const float*)d_in[6];
    const float* var1   = (const float*)d_in[7];
    const float* w_up   = (const float*)d_in[8];
    const float* gamma2 = (const float*)d_in[9];
    const float* beta2  = (const float*)d_in[10];
    const float* mean2  = (const float*)d_in[11];
    const float* var2   = (const float*)d_in[12];

    float* yout  = (float*)d_out;
    float* upout = yout + Y_ELEMS;

    k_prep_wA<<<4096, 256>>>(w_up);
    k_prep_wD<<<2304, 256>>>(w_dcn);
    k_off<<<BATCH * 16, 256>>>(x, w_off, b_off);
    k_deform_mma<<<512, 256>>>(x, gamma1, beta1, mean1, var1, yout);
    k_deconv_mma<<<2048, 256>>>(yout, gamma2, beta2, mean2, var2, upout);
}

// round 6
// speedup vs baseline: 1.4363x; 1.4363x over previous
#include <cuda_runtime.h>
#include <cuda_bf16.h>
#include <math.h>
#include <stdint.h>

// Problem constants
#define BATCH 8
#define CIN   256
#define COUT  256
#define H     64
#define W     64
#define KTAP  9
#define Y_ELEMS (BATCH*COUT*H*W)          // 8388608

// Scratch (device globals — no cudaMalloc allowed)
__device__ float g_offmask[BATCH * 27 * H * W];       // 3.5 MB
// Deconv A in per-thread MMA fragment order (tf32 bits):
// [cls(4)][mt(2)][ks(128)][m16t(8)][lane(32)][frag(4)]  = 4 MB
__device__ uint32_t g_wA[4 * 2 * 128 * 8 * 32 * 4];
// Deform A in per-thread MMA fragment order (tf32 bits):
// [mt(2)][ks(288)][m16t(8)][lane(32)][frag(4)]  = 2.36 MB
__device__ uint32_t g_wD[2 * 288 * 8 * 32 * 4];
// Offset-conv A (w_off, M=32 padded from 27, K=4096 = 256 ch * 16 padded taps):
// [ks(512)][m16t(2)][lane(32)][frag(4)]  = 512 KB
__device__ uint32_t g_wO[512 * 2 * 32 * 4];

// ---------------------------------------------------------------------------
// MMA helpers (sm_80 baseline PTX — legal on plain sm_103 target)
// ---------------------------------------------------------------------------
__device__ __forceinline__ uint32_t f2tf32(float v) {
    uint32_t u;
    asm("cvt.rna.tf32.f32 %0, %1;" : "=r"(u) : "f"(v));
    return u;
}
__device__ __forceinline__ void mma_tf32(float& d0, float& d1, float& d2, float& d3,
                                         uint32_t a0, uint32_t a1, uint32_t a2, uint32_t a3,
                                         uint32_t b0, uint32_t b1) {
    asm volatile("mma.sync.aligned.m16n8k8.row.col.f32.tf32.tf32.f32 "
                 "{%0,%1,%2,%3}, {%4,%5,%6,%7}, {%8,%9}, {%0,%1,%2,%3};"
                 : "+f"(d0), "+f"(d1), "+f"(d2), "+f"(d3)
                 : "r"(a0), "r"(a1), "r"(a2), "r"(a3), "r"(b0), "r"(b1));
}

// ---------------------------------------------------------------------------
// Kernel 0b: bake deconv A into per-thread tf32 fragment order.  (R4 layout)
// kk = c*4 + s*2 + t;  A[o][kk] = w_up[c][o][3-(a+2s)][3-(qb+2t)]
// ---------------------------------------------------------------------------
__global__ void k_prep_wA(const float* __restrict__ w_up) {
    int e = blockIdx.x * 256 + threadIdx.x;   // 1,048,576 total
    int frag = e & 3;
    int lane = (e >> 2) & 31;
    int m16t = (e >> 7) & 7;
    int ks   = (e >> 10) & 127;
    int mt   = (e >> 17) & 1;
    int cls  = e >> 18;
    int a = cls >> 1, qb = cls & 1;
    int g = lane >> 2, tg = lane & 3;
    int row = m16t * 16 + g + 8 * (frag & 1);
    int kcol = tg + 4 * (frag >> 1);
    int kk = ks * 8 + kcol;
    int c = kk >> 2, s = (kk >> 1) & 1, t = kk & 1;
    int o = mt * 128 + row;
    float val = w_up[((c << 8) + o) * 16 + (3 - (a + 2 * s)) * 4 + (3 - (qb + 2 * t))];
    g_wA[e] = f2tf32(val);
}

// ---------------------------------------------------------------------------
// Kernel 0c: bake deform A (w_dcn) into per-thread tf32 fragment order. (R4)
// ---------------------------------------------------------------------------
__global__ void k_prep_wD(const float* __restrict__ w_dcn) {
    int e = blockIdx.x * 256 + threadIdx.x;   // 589,824 total
    if (e >= 2 * 288 * 8 * 32 * 4) return;
    int frag = e & 3;
    int lane = (e >> 2) & 31;
    int m16t = (e >> 7) & 7;
    int rest = e >> 10;                 // 0..575
    int ks = rest % 288;
    int mt = rest / 288;
    int g = lane >> 2, tg = lane & 3;
    int row = m16t * 16 + g + 8 * (frag & 1);
    int kcol = tg + 4 * (frag >> 1);
    int kk = ks * 8 + kcol;             // 0..2303
    int c = kk / 9;
    int k = kk - c * 9;
    int o = mt * 128 + row;
    g_wD[e] = f2tf32(w_dcn[(o * 256 + c) * 9 + k]);
}

// ---------------------------------------------------------------------------
// Kernel 0d: bake offset-conv A (w_off) fragments. M=32 (27 real), K=4096
// (kk = c*16 + tap, taps 9..15 zero padding).
// ---------------------------------------------------------------------------
__global__ void k_prep_wO(const float* __restrict__ w_off) {
    int e = blockIdx.x * 256 + threadIdx.x;   // 131,072 total
    if (e >= 512 * 2 * 32 * 4) return;
    int frag = e & 3;
    int lane = (e >> 2) & 31;
    int m16t = (e >> 7) & 1;
    int ks   = e >> 8;                  // 0..511
    int g = lane >> 2, tg = lane & 3;
    int o = m16t * 16 + g + 8 * (frag & 1);
    int kcol = tg + 4 * (frag >> 1);
    int kk = ks * 8 + kcol;             // 0..4095
    int c = kk >> 4;
    int tap = kk & 15;
    float val = (tap < 9 && o < 27) ? w_off[(o * 256 + c) * 9 + tap] : 0.f;
    g_wO[e] = f2tf32(val);
}

// ---------------------------------------------------------------------------
// Kernel 1 (NEW): offset conv via mma.sync tf32 GEMM + bias -> g_offmask.
// Grid 128: [b(8)][ht(16)].  CTA: M=32, N=256 px (4 rows), K=4096
// (one channel per 16-wide chunk).  8 warps each own N=32.
// B fill: plain 3x3 im2col, 9 predicated LDGs per thread per chunk.
// ---------------------------------------------------------------------------
__global__ void __launch_bounds__(256) k_off_mma(const float* __restrict__ x,
                                                 const float* __restrict__ b_off) {
    __shared__ uint32_t Bs[2][256 * 20];

    int tid = threadIdx.x;
    int wid = tid >> 5, lane = tid & 31;
    int g = lane >> 2, tg = lane & 3;
    int warpN = wid;

    int bidx = blockIdx.x;
    int ht = bidx & 15;
    int b = bidx >> 4;
    int h0 = ht << 2;
    int pix0 = h0 << 6;

    // zero the K-padding columns (taps 9..15) once; never rewritten
    {
        int nn = tid;
#pragma unroll
        for (int kl = 9; kl < 16; kl++) {
            Bs[0][nn * 20 + kl] = 0;
            Bs[1][nn * 20 + kl] = 0;
        }
    }

    // per-thread pixel: r = row in tile, wc = col
    int r = tid >> 6, wc = tid & 63;
    const float* xb = x + (b << 20);

    float acc[2][4][4];
#pragma unroll
    for (int i = 0; i < 2; i++)
#pragma unroll
        for (int j = 0; j < 4; j++)
#pragma unroll
            for (int f = 0; f < 4; f++) acc[i][j][f] = 0.f;

    // window loader for channel c -> pv[9]
    auto loadwin = [&](int c, float* pv) {
        const float* xp = xb + (c << 12);
#pragma unroll
        for (int kh = 0; kh < 3; kh++) {
            int hh = h0 + r - 1 + kh;
            bool rok = (hh >= 0 && hh < H);
#pragma unroll
            for (int kw = 0; kw < 3; kw++) {
                int ww = wc - 1 + kw;
                float v = 0.f;
                if (rok && ww >= 0 && ww < W) v = __ldg(xp + (hh << 6) + ww);
                pv[kh * 3 + kw] = v;
            }
        }
    };

    // fill chunk 0
    {
        float pv[9];
        loadwin(0, pv);
#pragma unroll
        for (int t = 0; t < 9; t++) Bs[0][tid * 20 + t] = f2tf32(pv[t]);
    }
    __syncthreads();

    for (int chunk = 0; chunk < 256; chunk++) {
        int cur = chunk & 1;
        float pv[9];
        if (chunk < 255) loadwin(chunk + 1, pv);
        // MMA over 2 ksteps
#pragma unroll
        for (int ksv = 0; ksv < 2; ksv++) {
            int ks = chunk * 2 + ksv;
            uint32_t af[2][4];
#pragma unroll
            for (int mtl = 0; mtl < 2; mtl++) {
                uint4 q = *(const uint4*)(g_wO + ((ks * 2 + mtl) * 32 + lane) * 4);
                af[mtl][0] = q.x; af[mtl][1] = q.y; af[mtl][2] = q.z; af[mtl][3] = q.w;
            }
            uint32_t bf[4][2];
#pragma unroll
            for (int nt = 0; nt < 4; nt++) {
                int nrow = warpN * 32 + nt * 8 + g;
                bf[nt][0] = Bs[cur][nrow * 20 + ksv * 8 + tg];
                bf[nt][1] = Bs[cur][nrow * 20 + ksv * 8 + tg + 4];
            }
#pragma unroll
            for (int mtl = 0; mtl < 2; mtl++)
#pragma unroll
                for (int nt = 0; nt < 4; nt++)
                    mma_tf32(acc[mtl][nt][0], acc[mtl][nt][1], acc[mtl][nt][2], acc[mtl][nt][3],
                             af[mtl][0], af[mtl][1], af[mtl][2], af[mtl][3],
                             bf[nt][0], bf[nt][1]);
        }
        if (chunk < 255) {
            int nxt = cur ^ 1;
#pragma unroll
            for (int t = 0; t < 9; t++) Bs[nxt][tid * 20 + t] = f2tf32(pv[t]);
        }
        __syncthreads();
    }

    // epilogue: add bias, store 27 channels
#pragma unroll
    for (int mtl = 0; mtl < 2; mtl++)
#pragma unroll
        for (int hh = 0; hh < 2; hh++) {
            int o = mtl * 16 + g + hh * 8;
            if (o < 27) {
                float bo = __ldg(b_off + o);
                float* ob = g_offmask + ((b * 27 + o) << 12) + pix0;
#pragma unroll
                for (int nt = 0; nt < 4; nt++)
#pragma unroll
                    for (int cc = 0; cc < 2; cc++) {
                        int n = warpN * 32 + nt * 8 + 2 * tg + cc;
                        ob[n] = acc[mtl][nt][hh * 2 + cc] + bo;
                    }
            }
        }
}

// ---------------------------------------------------------------------------
// Kernel 2: deformable conv via mma.sync tf32 GEMM + BN1 + ReLU.  (R4 config)
// Grid 512: [b(8)][mt(2)][pt(32)].  CTA: M=128, N=128 px (2 rows), K=2304.
// ---------------------------------------------------------------------------
__global__ void __launch_bounds__(256) k_deform_mma(const float* __restrict__ x,
                                                    const float* __restrict__ g1,
                                                    const float* __restrict__ be1,
                                                    const float* __restrict__ m1,
                                                    const float* __restrict__ v1,
                                                    float* __restrict__ yout) {
    __shared__ ushort4 s_idx[1152];     // [pix(128)][tap(9)]
    __shared__ float4  s_wgt[1152];
    __shared__ uint32_t Bs[2][128 * 20];

    int tid = threadIdx.x;
    int wid = tid >> 5, lane = tid & 31;
    int g = lane >> 2, tg = lane & 3;
    int warpM = wid >> 2, warpN = wid & 3;

    int bidx = blockIdx.x;
    int pt = bidx & 31;
    int mt = (bidx >> 5) & 1;
    int b  = bidx >> 6;
    int pix0 = pt << 7;
    int h0 = pix0 >> 6;                 // two rows: h0, h0+1

    // ---- Phase A: tap table ----
    for (int e = tid; e < 1152; e += 256) {
        int pix = e / 9, tap = e - pix * 9;
        int h = h0 + (pix >> 6), w = pix & 63;
        const float* om = g_offmask + (b * 27) * 4096 + (h << 6) + w;
        float dy = om[tap * 4096];
        float dx = om[(9 + tap) * 4096];
        float ms = om[(18 + tap) * 4096];
        float m = 1.f / (1.f + expf(-ms));
        float py = dy + (float)(tap / 3 - 1 + h);
        float px = dx + (float)(tap % 3 - 1 + w);
        float fy = floorf(py), fx = floorf(px);
        float wy = py - fy, wx = px - fx;
        int y0 = (int)fy, x0 = (int)fx;
        int y1 = y0 + 1, x1 = x0 + 1;
        float vy0 = (y0 >= 0 && y0 < H) ? 1.f : 0.f;
        float vy1 = (y1 >= 0 && y1 < H) ? 1.f : 0.f;
        float vx0 = (x0 >= 0 && x0 < W) ? 1.f : 0.f;
        float vx1 = (x1 >= 0 && x1 < W) ? 1.f : 0.f;
        int cy0 = min(max(y0, 0), H - 1), cy1 = min(max(y1, 0), H - 1);
        int cx0 = min(max(x0, 0), W - 1), cx1 = min(max(x1, 0), W - 1);
        ushort4 id;
        id.x = (unsigned short)((cy0 << 6) + cx0);
        id.y = (unsigned short)((cy0 << 6) + cx1);
        id.z = (unsigned short)((cy1 << 6) + cx0);
        id.w = (unsigned short)((cy1 << 6) + cx1);
        s_idx[e] = id;
        float4 wv;
        wv.x = (1.f - wy) * (1.f - wx) * m * vy0 * vx0;
        wv.y = (1.f - wy) * wx * m * vy0 * vx1;
        wv.z = wy * (1.f - wx) * m * vy1 * vx0;
        wv.w = wy * wx * m * vy1 * vx1;
        s_wgt[e] = wv;
    }
    __syncthreads();

    // ---- B fill mapping: 16 kl x 16 nb, 8 pixels each ----
    int kl = tid & 15;
    int nb = tid >> 4;
    int n0 = nb << 3;
    const float* xb = x + (b << 20);

    float acc[4][4][4];
#pragma unroll
    for (int i = 0; i < 4; i++)
#pragma unroll
        for (int j = 0; j < 4; j++)
#pragma unroll
            for (int f = 0; f < 4; f++) acc[i][j][f] = 0.f;

    // fill chunk 0
    {
        int kk = kl;
        int c = kk / 9, tap = kk - c * 9;
        const float* xp = xb + (c << 12);
#pragma unroll
        for (int j = 0; j < 8; j++) {
            int e = (n0 + j) * 9 + tap;
            ushort4 id = s_idx[e];
            float4 wv = s_wgt[e];
            float v = wv.x * __ldg(xp + id.x) + wv.y * __ldg(xp + id.y) +
                      wv.z * __ldg(xp + id.z) + wv.w * __ldg(xp + id.w);
            Bs[0][(n0 + j) * 20 + kl] = f2tf32(v);
        }
    }
    __syncthreads();

    const uint32_t* Afrag = g_wD + mt * (288 * 8 * 32 * 4);

    for (int chunk = 0; chunk < 144; chunk++) {
        int cur = chunk & 1;
        float pv[8];
        if (chunk < 143) {
            int kk = (chunk + 1) * 16 + kl;
            int c = kk / 9, tap = kk - c * 9;
            const float* xp = xb + (c << 12);
#pragma unroll
            for (int j = 0; j < 8; j++) {
                int e = (n0 + j) * 9 + tap;
                ushort4 id = s_idx[e];
                float4 wv = s_wgt[e];
                pv[j] = wv.x * __ldg(xp + id.x) + wv.y * __ldg(xp + id.y) +
                        wv.z * __ldg(xp + id.z) + wv.w * __ldg(xp + id.w);
            }
        }
#pragma unroll
        for (int ksv = 0; ksv < 2; ksv++) {
            uint32_t af[4][4];
#pragma unroll
            for (int mtl = 0; mtl < 4; mtl++) {
                uint4 q = *(const uint4*)(Afrag +
                    ((((chunk * 2 + ksv) * 8) + warpM * 4 + mtl) * 32 + lane) * 4);
                af[mtl][0] = q.x; af[mtl][1] = q.y; af[mtl][2] = q.z; af[mtl][3] = q.w;
            }
            uint32_t bf[4][2];
#pragma unroll
            for (int nt = 0; nt < 4; nt++) {
                int nrow = warpN * 32 + nt * 8 + g;
                bf[nt][0] = Bs[cur][nrow * 20 + ksv * 8 + tg];
                bf[nt][1] = Bs[cur][nrow * 20 + ksv * 8 + tg + 4];
            }
#pragma unroll
            for (int mtl = 0; mtl < 4; mtl++)
#pragma unroll
                for (int nt = 0; nt < 4; nt++)
                    mma_tf32(acc[mtl][nt][0], acc[mtl][nt][1], acc[mtl][nt][2], acc[mtl][nt][3],
                             af[mtl][0], af[mtl][1], af[mtl][2], af[mtl][3],
                             bf[nt][0], bf[nt][1]);
        }
        if (chunk < 143) {
            int nxt = cur ^ 1;
#pragma unroll
            for (int j = 0; j < 8; j++)
                Bs[nxt][(n0 + j) * 20 + kl] = f2tf32(pv[j]);
        }
        __syncthreads();
    }

    // ---- epilogue: BN1 + ReLU ----
#pragma unroll
    for (int mtl = 0; mtl < 4; mtl++)
#pragma unroll
        for (int hh = 0; hh < 2; hh++) {
            int o = mt * 128 + warpM * 64 + mtl * 16 + g + hh * 8;
            float s_ = __ldg(g1 + o) * rsqrtf(__ldg(v1 + o) + 1e-5f);
            float sh = __ldg(be1 + o) - __ldg(m1 + o) * s_;
            float* ob = yout + (((b << 8) + o) << 12) + pix0;
#pragma unroll
            for (int nt = 0; nt < 4; nt++)
#pragma unroll
                for (int cc = 0; cc < 2; cc++) {
                    int n = warpN * 32 + nt * 8 + 2 * tg + cc;
                    float v = acc[mtl][nt][hh * 2 + cc];
                    ob[n] = fmaxf(fmaf(v, s_, sh), 0.f);
                }
        }
}

// ---------------------------------------------------------------------------
// Kernel 3: transposed conv via mma.sync tf32 GEMM + BN2 + ReLU.  (R4 config)
// Grid 2048: [cls(4)][b(8)][mt(2)][pt(32)].  CTA: M=128, N=128, K=1024.
// ---------------------------------------------------------------------------
__global__ void __launch_bounds__(256) k_deconv_mma(const float* __restrict__ y,
                                                    const float* __restrict__ g2,
                                                    const float* __restrict__ be2,
                                                    const float* __restrict__ m2,
                                                    const float* __restrict__ v2,
                                                    float* __restrict__ up) {
    __shared__ uint32_t Bs[2][128 * 20];

    int tid = threadIdx.x;
    int wid = tid >> 5, lane = tid & 31;
    int g = lane >> 2, tg = lane & 3;
    int warpM = wid >> 2, warpN = wid & 3;

    int bidx = blockIdx.x;
    int pt  = bidx & 31;
    int mt  = (bidx >> 5) & 1;
    int b   = (bidx >> 6) & 7;
    int cls = bidx >> 9;
    int a = cls >> 1, qb = cls & 1;
    int pp0 = pt << 1;

    int kl = tid & 15;
    int nb = tid >> 4;
    int c_l = kl >> 2, s = (kl >> 1) & 1, t = kl & 1;
    int pr = nb >> 3;
    int qq0 = (nb & 7) << 3;
    int n0 = nb << 3;
    int iy = pp0 + pr + s + a - 1;
    bool rowok = (iy >= 0 && iy < H);
    const float* ybase = y + ((b << 8) << 12) + (iy << 6);
    int ix0 = qq0 + qb - 1 + t;

    float acc[4][4][4];
#pragma unroll
    for (int i = 0; i < 4; i++)
#pragma unroll
        for (int j = 0; j < 4; j++)
#pragma unroll
            for (int f = 0; f < 4; f++) acc[i][j][f] = 0.f;

    {
        const float* yr = ybase + (c_l << 12);
#pragma unroll
        for (int j = 0; j < 8; j++) {
            int ix = ix0 + j;
            float v = (rowok && ix >= 0 && ix < W) ? __ldg(yr + ix) : 0.f;
            Bs[0][(n0 + j) * 20 + kl] = f2tf32(v);
        }
    }
    __syncthreads();

    const uint32_t* Afrag = g_wA + (cls * 2 + mt) * (128 * 8 * 32 * 4);

    for (int chunk = 0; chunk < 64; chunk++) {
        int cur = chunk & 1;
        float pv[8];
        if (chunk < 63) {
            const float* yr = ybase + (((chunk + 1) * 4 + c_l) << 12);
#pragma unroll
            for (int j = 0; j < 8; j++) {
                int ix = ix0 + j;
                pv[j] = (rowok && ix >= 0 && ix < W) ? __ldg(yr + ix) : 0.f;
            }
        }
        uint32_t af[2][4][4];
#pragma unroll
        for (int ksv = 0; ksv < 2; ksv++)
#pragma unroll
            for (int mtl = 0; mtl < 4; mtl++) {
                uint4 q = *(const uint4*)(Afrag +
                    ((((chunk * 2 + ksv) * 8) + warpM * 4 + mtl) * 32 + lane) * 4);
                af[ksv][mtl][0] = q.x; af[ksv][mtl][1] = q.y;
                af[ksv][mtl][2] = q.z; af[ksv][mtl][3] = q.w;
            }
#pragma unroll
        for (int ksv = 0; ksv < 2; ksv++) {
            uint32_t bf[4][2];
#pragma unroll
            for (int nt = 0; nt < 4; nt++) {
                int nrow = warpN * 32 + nt * 8 + g;
                bf[nt][0] = Bs[cur][nrow * 20 + ksv * 8 + tg];
                bf[nt][1] = Bs[cur][nrow * 20 + ksv * 8 + tg + 4];
            }
#pragma unroll
            for (int mtl = 0; mtl < 4; mtl++)
#pragma unroll
                for (int nt = 0; nt < 4; nt++)
                    mma_tf32(acc[mtl][nt][0], acc[mtl][nt][1], acc[mtl][nt][2], acc[mtl][nt][3],
                             af[ksv][mtl][0], af[ksv][mtl][1], af[ksv][mtl][2], af[ksv][mtl][3],
                             bf[nt][0], bf[nt][1]);
        }
        if (chunk < 63) {
            int nxt = cur ^ 1;
#pragma unroll
            for (int j = 0; j < 8; j++)
                Bs[nxt][(n0 + j) * 20 + kl] = f2tf32(pv[j]);
        }
        __syncthreads();
    }

    float sc[4][2], sh[4][2];
#pragma unroll
    for (int mtl = 0; mtl < 4; mtl++)
#pragma unroll
        for (int hh = 0; hh < 2; hh++) {
            int o = mt * 128 + warpM * 64 + mtl * 16 + g + hh * 8;
            float s_ = __ldg(g2 + o) * rsqrtf(__ldg(v2 + o) + 1e-5f);
            sc[mtl][hh] = s_;
            sh[mtl][hh] = __ldg(be2 + o) - __ldg(m2 + o) * s_;
        }
#pragma unroll
    for (int mtl = 0; mtl < 4; mtl++)
#pragma unroll
        for (int hh = 0; hh < 2; hh++) {
            int o = mt * 128 + warpM * 64 + mtl * 16 + g + hh * 8;
            float* ob = up + (((b << 8) + o) << 14);
#pragma unroll
            for (int nt = 0; nt < 4; nt++)
#pragma unroll
                for (int cc = 0; cc < 2; cc++) {
                    int n = warpN * 32 + nt * 8 + 2 * tg + cc;
                    int prr = n >> 6, qqv = n & 63;
                    int p = ((pp0 + prr) << 1) + a;
                    int qv = (qqv << 1) + qb;
                    float v = acc[mtl][nt][hh * 2 + cc];
                    ob[(p << 7) + qv] = fmaxf(fmaf(v, sc[mtl][hh], sh[mtl][hh]), 0.f);
                }
        }
}

// ---------------------------------------------------------------------------
extern "C" void kernel_launch(void* const* d_in, const int* in_sizes, int n_in,
                              void* d_out, int out_size) {
    const float* x      = (const float*)d_in[0];
    const float* w_off  = (const float*)d_in[1];
    const float* b_off  = (const float*)d_in[2];
    const float* w_dcn  = (const float*)d_in[3];
    const float* gamma1 = (const float*)d_in[4];
    const float* beta1  = (const float*)d_in[5];
    const float* mean1  = (const float*)d_in[6];
    const float* var1   = (const float*)d_in[7];
    const float* w_up   = (const float*)d_in[8];
    const float* gamma2 = (const float*)d_in[9];
    const float* beta2  = (const float*)d_in[10];
    const float* mean2  = (const float*)d_in[11];
    const float* var2   = (const float*)d_in[12];

    float* yout  = (float*)d_out;
    float* upout = yout + Y_ELEMS;

    k_prep_wA<<<4096, 256>>>(w_up);
    k_prep_wD<<<2304, 256>>>(w_dcn);
    k_prep_wO<<<512, 256>>>(w_off);
    k_off_mma<<<128, 256>>>(x, b_off);
    k_deform_mma<<<512, 256>>>(x, gamma1, beta1, mean1, var1, yout);
    k_deconv_mma<<<2048, 256>>>(yout, gamma2, beta2, mean2, var2, upout);
}

// round 8
// speedup vs baseline: 1.5440x; 1.0750x over previous
#include <cuda_runtime.h>
#include <cuda_bf16.h>
#include <math.h>
#include <stdint.h>

// Problem constants
#define BATCH 8
#define CIN   256
#define COUT  256
#define H     64
#define W     64
#define KTAP  9
#define Y_ELEMS (BATCH*COUT*H*W)          // 8388608

// Scratch (device globals — no cudaMalloc allowed)
__device__ float g_offmask[BATCH * 27 * H * W];       // 3.5 MB
// Deconv A in per-thread MMA fragment order (tf32 bits):
// [cls(4)][mt(2)][ks(128)][m16t(8)][lane(32)][frag(4)]  = 4 MB
__device__ uint32_t g_wA[4 * 2 * 128 * 8 * 32 * 4];
// Deform A (K padded to 16 per channel): [mt(2)][ks(512)][m16t(8)][lane(32)][frag(4)] = 8 MB
#define WD2_ELEMS (2 * 512 * 8 * 32 * 4)
__device__ uint32_t g_wD2[WD2_ELEMS];
// Offset-conv A (M=32 padded from 27, K=4096 = 256 ch * 16 padded taps):
// [ks(512)][m16t(2)][lane(32)][frag(4)]  = 512 KB
__device__ uint32_t g_wO[512 * 2 * 32 * 4];

// ---------------------------------------------------------------------------
// Helpers
// ---------------------------------------------------------------------------
__device__ __forceinline__ uint32_t f2tf32(float v) {
    uint32_t u;
    asm("cvt.rna.tf32.f32 %0, %1;" : "=r"(u) : "f"(v));
    return u;
}
__device__ __forceinline__ void mma_tf32(float& d0, float& d1, float& d2, float& d3,
                                         uint32_t a0, uint32_t a1, uint32_t a2, uint32_t a3,
                                         uint32_t b0, uint32_t b1) {
    asm volatile("mma.sync.aligned.m16n8k8.row.col.f32.tf32.tf32.f32 "
                 "{%0,%1,%2,%3}, {%4,%5,%6,%7}, {%8,%9}, {%0,%1,%2,%3};"
                 : "+f"(d0), "+f"(d1), "+f"(d2), "+f"(d3)
                 : "r"(a0), "r"(a1), "r"(a2), "r"(a3), "r"(b0), "r"(b1));
}
__device__ __forceinline__ uint32_t smem_u32(const void* p) {
    uint32_t a;
    asm("{ .reg .u64 t; cvta.to.shared.u64 t, %1; cvt.u32.u64 %0, t; }" : "=r"(a) : "l"(p));
    return a;
}
#define CP_ASYNC16(dst_u32, src_ptr) \
    asm volatile("cp.async.cg.shared.global [%0], [%1], 16;" :: "r"(dst_u32), "l"(src_ptr))
#define CP_COMMIT() asm volatile("cp.async.commit_group;" ::: "memory")
#define CP_WAIT0()  asm volatile("cp.async.wait_group 0;" ::: "memory")

// ---------------------------------------------------------------------------
// Kernel 0b: bake deconv A into per-thread tf32 fragment order.
// ---------------------------------------------------------------------------
__global__ void k_prep_wA(const float* __restrict__ w_up) {
    int e = blockIdx.x * 256 + threadIdx.x;   // 1,048,576 total
    int frag = e & 3;
    int lane = (e >> 2) & 31;
    int m16t = (e >> 7) & 7;
    int ks   = (e >> 10) & 127;
    int mt   = (e >> 17) & 1;
    int cls  = e >> 18;
    int a = cls >> 1, qb = cls & 1;
    int g = lane >> 2, tg = lane & 3;
    int row = m16t * 16 + g + 8 * (frag & 1);
    int kcol = tg + 4 * (frag >> 1);
    int kk = ks * 8 + kcol;
    int c = kk >> 2, s = (kk >> 1) & 1, t = kk & 1;
    int o = mt * 128 + row;
    float val = w_up[((c << 8) + o) * 16 + (3 - (a + 2 * s)) * 4 + (3 - (qb + 2 * t))];
    g_wA[e] = f2tf32(val);
}

// ---------------------------------------------------------------------------
// Kernel 0c: bake deform A, K padded per channel to 16 (kk = c*16 + tap).
// FIXED: exact element count + bounds guard.
// ---------------------------------------------------------------------------
__global__ void k_prep_wD(const float* __restrict__ w_dcn) {
    int e = blockIdx.x * 256 + threadIdx.x;   // 1,048,576 total (4096 blocks)
    if (e >= WD2_ELEMS) return;
    int frag = e & 3;
    int lane = (e >> 2) & 31;
    int m16t = (e >> 7) & 7;
    int ks   = (e >> 10) & 511;
    int mt   = (e >> 19) & 1;
    int g = lane >> 2, tg = lane & 3;
    int row = m16t * 16 + g + 8 * (frag & 1);
    int kcol = tg + 4 * (frag >> 1);
    int kk = ks * 8 + kcol;              // 0..4095
    int c = kk >> 4, tap = kk & 15;
    int o = mt * 128 + row;
    float val = (tap < 9) ? w_dcn[(o * 256 + c) * 9 + tap] : 0.f;
    g_wD2[e] = f2tf32(val);
}

// ---------------------------------------------------------------------------
// Kernel 0d: bake offset-conv A (w_off).
// ---------------------------------------------------------------------------
__global__ void k_prep_wO(const float* __restrict__ w_off) {
    int e = blockIdx.x * 256 + threadIdx.x;   // 131,072 total
    if (e >= 512 * 2 * 32 * 4) return;
    int frag = e & 3;
    int lane = (e >> 2) & 31;
    int m16t = (e >> 7) & 1;
    int ks   = e >> 8;                  // 0..511
    int g = lane >> 2, tg = lane & 3;
    int o = m16t * 16 + g + 8 * (frag & 1);
    int kcol = tg + 4 * (frag >> 1);
    int kk = ks * 8 + kcol;             // 0..4095
    int c = kk >> 4;
    int tap = kk & 15;
    float val = (tap < 9 && o < 27) ? w_off[(o * 256 + c) * 9 + tap] : 0.f;
    g_wO[e] = f2tf32(val);
}

// ---------------------------------------------------------------------------
// Kernel 1: offset conv MMA GEMM, 2-row tiles, 2-channel chunks.
// Grid 256: [b(8)][ht(32)].  CTA: M=32, N=128 px, K=4096, chunk=32 (2 ch).
// ---------------------------------------------------------------------------
__global__ void __launch_bounds__(256) k_off_mma(const float* __restrict__ x,
                                                 const float* __restrict__ b_off) {
    __shared__ uint32_t Bs[2][128 * 37];   // 37 KB

    int tid = threadIdx.x;
    int wid = tid >> 5, lane = tid & 31;
    int g = lane >> 2, tg = lane & 3;

    int bidx = blockIdx.x;
    int ht = bidx & 31;
    int b = bidx >> 5;
    int h0 = ht << 1;
    int pix0 = h0 << 6;

    int chalf = tid >> 7;
    int pix = tid & 127;
    int r = pix >> 6, wc = pix & 63;
    const float* xb = x + (b << 20);

#pragma unroll
    for (int t = 9; t < 16; t++) {
        Bs[0][pix * 37 + chalf * 16 + t] = 0;
        Bs[1][pix * 37 + chalf * 16 + t] = 0;
    }

    float acc[2][2][4];
#pragma unroll
    for (int i = 0; i < 2; i++)
#pragma unroll
        for (int j = 0; j < 2; j++)
#pragma unroll
            for (int f = 0; f < 4; f++) acc[i][j][f] = 0.f;

    auto loadwin = [&](int c, float* pv) {
        const float* xp = xb + (c << 12);
#pragma unroll
        for (int kh = 0; kh < 3; kh++) {
            int hh = h0 + r - 1 + kh;
            bool rok = (hh >= 0 && hh < H);
#pragma unroll
            for (int kw = 0; kw < 3; kw++) {
                int ww = wc - 1 + kw;
                float v = 0.f;
                if (rok && ww >= 0 && ww < W) v = __ldg(xp + (hh << 6) + ww);
                pv[kh * 3 + kw] = v;
            }
        }
    };

    {
        float pv[9];
        loadwin(chalf, pv);
#pragma unroll
        for (int t = 0; t < 9; t++) Bs[0][pix * 37 + chalf * 16 + t] = f2tf32(pv[t]);
    }
    __syncthreads();

    for (int chunk = 0; chunk < 128; chunk++) {
        int cur = chunk & 1;
        float pv[9];
        if (chunk < 127) loadwin((chunk + 1) * 2 + chalf, pv);
#pragma unroll
        for (int ksv = 0; ksv < 4; ksv++) {
            int ks = chunk * 4 + ksv;
            uint32_t af[2][4];
#pragma unroll
            for (int mtl = 0; mtl < 2; mtl++) {
                uint4 q = *(const uint4*)(g_wO + ((ks * 2 + mtl) * 32 + lane) * 4);
                af[mtl][0] = q.x; af[mtl][1] = q.y; af[mtl][2] = q.z; af[mtl][3] = q.w;
            }
            uint32_t bf[2][2];
#pragma unroll
            for (int nt = 0; nt < 2; nt++) {
                int nrow = wid * 16 + nt * 8 + g;
                bf[nt][0] = Bs[cur][nrow * 37 + ksv * 8 + tg];
                bf[nt][1] = Bs[cur][nrow * 37 + ksv * 8 + tg + 4];
            }
#pragma unroll
            for (int mtl = 0; mtl < 2; mtl++)
#pragma unroll
                for (int nt = 0; nt < 2; nt++)
                    mma_tf32(acc[mtl][nt][0], acc[mtl][nt][1], acc[mtl][nt][2], acc[mtl][nt][3],
                             af[mtl][0], af[mtl][1], af[mtl][2], af[mtl][3],
                             bf[nt][0], bf[nt][1]);
        }
        if (chunk < 127) {
            int nxt = cur ^ 1;
#pragma unroll
            for (int t = 0; t < 9; t++) Bs[nxt][pix * 37 + chalf * 16 + t] = f2tf32(pv[t]);
        }
        __syncthreads();
    }

#pragma unroll
    for (int mtl = 0; mtl < 2; mtl++)
#pragma unroll
        for (int hh = 0; hh < 2; hh++) {
            int o = mtl * 16 + g + hh * 8;
            if (o < 27) {
                float bo = __ldg(b_off + o);
                float* ob = g_offmask + ((b * 27 + o) << 12) + pix0;
#pragma unroll
                for (int nt = 0; nt < 2; nt++)
#pragma unroll
                    for (int cc = 0; cc < 2; cc++) {
                        int n = wid * 16 + nt * 8 + 2 * tg + cc;
                        ob[n] = acc[mtl][nt][hh * 2 + cc] + bo;
                    }
            }
        }
}

// ---------------------------------------------------------------------------
// Kernel 2: deformable conv GEMM with SMEM channel staging.
// Grid 512: [b(8)][mt(2)][pt(32)].  CTA: M=128, N=128 px (2 rows),
// K=4096 (c*16+tap padded), chunk = 1 channel = 16 k.
// Dyn smem: stage 2x16KB @0, Bs 2x(128*20)w @32768, idx @53248, wgt @62464.
// ---------------------------------------------------------------------------
#define DEFORM_SMEM 80896
__global__ void __launch_bounds__(256) k_deform_mma(const float* __restrict__ x,
                                                    const float* __restrict__ g1,
                                                    const float* __restrict__ be1,
                                                    const float* __restrict__ m1,
                                                    const float* __restrict__ v1,
                                                    float* __restrict__ yout) {
    extern __shared__ char dsm[];
    float*    stage = (float*)dsm;                       // [2][4096]
    uint32_t* BsB   = (uint32_t*)(dsm + 32768);          // [2][2560]
    ushort4*  s_idx = (ushort4*)(dsm + 53248);           // [1152]
    float4*   s_wgt = (float4*)(dsm + 62464);            // [1152]

    int tid = threadIdx.x;
    int wid = tid >> 5, lane = tid & 31;
    int g = lane >> 2, tg = lane & 3;
    int warpM = wid >> 2, warpN = wid & 3;

    int bidx = blockIdx.x;
    int pt = bidx & 31;
    int mt = (bidx >> 5) & 1;
    int b  = bidx >> 6;
    int pix0 = pt << 7;
    int h0 = pix0 >> 6;                 // two rows: h0, h0+1

    // ---- Phase A: tap table ----
    for (int e = tid; e < 1152; e += 256) {
        int pix = e / 9, tap = e - pix * 9;
        int h = h0 + (pix >> 6), w = pix & 63;
        const float* om = g_offmask + (b * 27) * 4096 + (h << 6) + w;
        float dy = om[tap * 4096];
        float dx = om[(9 + tap) * 4096];
        float ms = om[(18 + tap) * 4096];
        float m = 1.f / (1.f + expf(-ms));
        float py = dy + (float)(tap / 3 - 1 + h);
        float px = dx + (float)(tap % 3 - 1 + w);
        float fy = floorf(py), fx = floorf(px);
        float wy = py - fy, wx = px - fx;
        int y0 = (int)fy, x0 = (int)fx;
        int y1 = y0 + 1, x1 = x0 + 1;
        float vy0 = (y0 >= 0 && y0 < H) ? 1.f : 0.f;
        float vy1 = (y1 >= 0 && y1 < H) ? 1.f : 0.f;
        float vx0 = (x0 >= 0 && x0 < W) ? 1.f : 0.f;
        float vx1 = (x1 >= 0 && x1 < W) ? 1.f : 0.f;
        int cy0 = min(max(y0, 0), H - 1), cy1 = min(max(y1, 0), H - 1);
        int cx0 = min(max(x0, 0), W - 1), cx1 = min(max(x1, 0), W - 1);
        ushort4 id;
        id.x = (unsigned short)((cy0 << 6) + cx0);
        id.y = (unsigned short)((cy0 << 6) + cx1);
        id.z = (unsigned short)((cy1 << 6) + cx0);
        id.w = (unsigned short)((cy1 << 6) + cx1);
        s_idx[e] = id;
        float4 wv;
        wv.x = (1.f - wy) * (1.f - wx) * m * vy0 * vx0;
        wv.y = (1.f - wy) * wx * m * vy0 * vx1;
        wv.z = wy * (1.f - wx) * m * vy1 * vx0;
        wv.w = wy * wx * m * vy1 * vx1;
        s_wgt[e] = wv;
    }
    // zero both Bs buffers (pad k-cols stay zero forever)
    for (int e = tid; e < 5120; e += 256) BsB[e] = 0;

    const float* xb = x + (b << 20);
    uint32_t stage_u = smem_u32(stage);

    // prologue: stage[0] <- channel 0 via cp.async
    {
        const float* src = xb;
#pragma unroll
        for (int i = 0; i < 4; i++) {
            int e4 = tid + (i << 8);
            CP_ASYNC16(stage_u + e4 * 16, src + e4 * 4);
        }
        CP_COMMIT();
    }

    // precompute gather slots (fixed per thread)
    int eo[5], bo[5];
#pragma unroll
    for (int ii = 0; ii < 5; ii++) {
        int e = tid + (ii << 8);
        eo[ii] = e;
        int pixe = e / 9;
        int tap = e - pixe * 9;
        bo[ii] = pixe * 20 + tap;
    }

    const uint32_t* Afrag = g_wD2 + mt * (512 * 8 * 32 * 4);

    float acc[4][4][4];
#pragma unroll
    for (int i = 0; i < 4; i++)
#pragma unroll
        for (int j = 0; j < 4; j++)
#pragma unroll
            for (int f = 0; f < 4; f++) acc[i][j][f] = 0.f;

    for (int c = 0; c < 256; c++) {
        int cur = c & 1;
        CP_WAIT0();
        __syncthreads();          // stage[cur] ready; Bs[cur] free
        if (c < 255) {
            const float* src = xb + ((c + 1) << 12);
            uint32_t dstb = stage_u + ((cur ^ 1) << 14);
#pragma unroll
            for (int i = 0; i < 4; i++) {
                int e4 = tid + (i << 8);
                CP_ASYNC16(dstb + e4 * 16, src + e4 * 4);
            }
            CP_COMMIT();
        }
        // gather from staged channel -> Bs[cur]
        const float* stg = stage + (cur << 12);
        uint32_t* Bc = BsB + cur * 2560;
#pragma unroll
        for (int ii = 0; ii < 5; ii++) {
            if (eo[ii] < 1152) {
                ushort4 id = s_idx[eo[ii]];
                float4 wv = s_wgt[eo[ii]];
                float v = wv.x * stg[id.x] + wv.y * stg[id.y] +
                          wv.z * stg[id.z] + wv.w * stg[id.w];
                Bc[bo[ii]] = f2tf32(v);
            }
        }
        __syncthreads();          // Bs[cur] ready
        // MMA: 2 ksteps
#pragma unroll
        for (int ksv = 0; ksv < 2; ksv++) {
            int ks = c * 2 + ksv;
            uint32_t af[4][4];
#pragma unroll
            for (int mtl = 0; mtl < 4; mtl++) {
                uint4 q = *(const uint4*)(Afrag + ((ks * 8 + warpM * 4 + mtl) * 32 + lane) * 4);
                af[mtl][0] = q.x; af[mtl][1] = q.y; af[mtl][2] = q.z; af[mtl][3] = q.w;
            }
            uint32_t bf[4][2];
#pragma unroll
            for (int nt = 0; nt < 4; nt++) {
                int nrow = warpN * 32 + nt * 8 + g;
                bf[nt][0] = Bc[nrow * 20 + ksv * 8 + tg];
                bf[nt][1] = Bc[nrow * 20 + ksv * 8 + tg + 4];
            }
#pragma unroll
            for (int mtl = 0; mtl < 4; mtl++)
#pragma unroll
                for (int nt = 0; nt < 4; nt++)
                    mma_tf32(acc[mtl][nt][0], acc[mtl][nt][1], acc[mtl][nt][2], acc[mtl][nt][3],
                             af[mtl][0], af[mtl][1], af[mtl][2], af[mtl][3],
                             bf[nt][0], bf[nt][1]);
        }
    }

    // ---- epilogue: BN1 + ReLU ----
#pragma unroll
    for (int mtl = 0; mtl < 4; mtl++)
#pragma unroll
        for (int hh = 0; hh < 2; hh++) {
            int o = mt * 128 + warpM * 64 + mtl * 16 + g + hh * 8;
            float s_ = __ldg(g1 + o) * rsqrtf(__ldg(v1 + o) + 1e-5f);
            float sh = __ldg(be1 + o) - __ldg(m1 + o) * s_;
            float* ob = yout + (((b << 8) + o) << 12) + pix0;
#pragma unroll
            for (int nt = 0; nt < 4; nt++)
#pragma unroll
                for (int cc = 0; cc < 2; cc++) {
                    int n = warpN * 32 + nt * 8 + 2 * tg + cc;
                    float v = acc[mtl][nt][hh * 2 + cc];
                    ob[n] = fmaxf(fmaf(v, s_, sh), 0.f);
                }
        }
}

// ---------------------------------------------------------------------------
// Kernel 3: transposed conv via mma.sync tf32 GEMM + BN2 + ReLU.
// Grid 2048: [cls(4)][b(8)][mt(2)][pt(32)].  CTA: M=128, N=128, K=1024.
// ---------------------------------------------------------------------------
__global__ void __launch_bounds__(256) k_deconv_mma(const float* __restrict__ y,
                                                    const float* __restrict__ g2,
                                                    const float* __restrict__ be2,
                                                    const float* __restrict__ m2,
                                                    const float* __restrict__ v2,
                                                    float* __restrict__ up) {
    __shared__ uint32_t Bs[2][128 * 20];

    int tid = threadIdx.x;
    int wid = tid >> 5, lane = tid & 31;
    int g = lane >> 2, tg = lane & 3;
    int warpM = wid >> 2, warpN = wid & 3;

    int bidx = blockIdx.x;
    int pt  = bidx & 31;
    int mt  = (bidx >> 5) & 1;
    int b   = (bidx >> 6) & 7;
    int cls = bidx >> 9;
    int a = cls >> 1, qb = cls & 1;
    int pp0 = pt << 1;

    int kl = tid & 15;
    int nb = tid >> 4;
    int c_l = kl >> 2, s = (kl >> 1) & 1, t = kl & 1;
    int pr = nb >> 3;
    int qq0 = (nb & 7) << 3;
    int n0 = nb << 3;
    int iy = pp0 + pr + s + a - 1;
    bool rowok = (iy >= 0 && iy < H);
    const float* ybase = y + ((b << 8) << 12) + (iy << 6);
    int ix0 = qq0 + qb - 1 + t;

    float acc[4][4][4];
#pragma unroll
    for (int i = 0; i < 4; i++)
#pragma unroll
        for (int j = 0; j < 4; j++)
#pragma unroll
            for (int f = 0; f < 4; f++) acc[i][j][f] = 0.f;

    {
        const float* yr = ybase + (c_l << 12);
#pragma unroll
        for (int j = 0; j < 8; j++) {
            int ix = ix0 + j;
            float v = (rowok && ix >= 0 && ix < W) ? __ldg(yr + ix) : 0.f;
            Bs[0][(n0 + j) * 20 + kl] = f2tf32(v);
        }
    }
    __syncthreads();

    const uint32_t* Afrag = g_wA + (cls * 2 + mt) * (128 * 8 * 32 * 4);

    for (int chunk = 0; chunk < 64; chunk++) {
        int cur = chunk & 1;
        float pv[8];
        if (chunk < 63) {
            const float* yr = ybase + (((chunk + 1) * 4 + c_l) << 12);
#pragma unroll
            for (int j = 0; j < 8; j++) {
                int ix = ix0 + j;
                pv[j] = (rowok && ix >= 0 && ix < W) ? __ldg(yr + ix) : 0.f;
            }
        }
        uint32_t af[2][4][4];
#pragma unroll
        for (int ksv = 0; ksv < 2; ksv++)
#pragma unroll
            for (int mtl = 0; mtl < 4; mtl++) {
                uint4 q = *(const uint4*)(Afrag +
                    ((((chunk * 2 + ksv) * 8) + warpM * 4 + mtl) * 32 + lane) * 4);
                af[ksv][mtl][0] = q.x; af[ksv][mtl][1] = q.y;
                af[ksv][mtl][2] = q.z; af[ksv][mtl][3] = q.w;
            }
#pragma unroll
        for (int ksv = 0; ksv < 2; ksv++) {
            uint32_t bf[4][2];
#pragma unroll
            for (int nt = 0; nt < 4; nt++) {
                int nrow = warpN * 32 + nt * 8 + g;
                bf[nt][0] = Bs[cur][nrow * 20 + ksv * 8 + tg];
                bf[nt][1] = Bs[cur][nrow * 20 + ksv * 8 + tg + 4];
            }
#pragma unroll
            for (int mtl = 0; mtl < 4; mtl++)
#pragma unroll
                for (int nt = 0; nt < 4; nt++)
                    mma_tf32(acc[mtl][nt][0], acc[mtl][nt][1], acc[mtl][nt][2], acc[mtl][nt][3],
                             af[ksv][mtl][0], af[ksv][mtl][1], af[ksv][mtl][2], af[ksv][mtl][3],
                             bf[nt][0], bf[nt][1]);
        }
        if (chunk < 63) {
            int nxt = cur ^ 1;
#pragma unroll
            for (int j = 0; j < 8; j++)
                Bs[nxt][(n0 + j) * 20 + kl] = f2tf32(pv[j]);
        }
        __syncthreads();
    }

    float sc[4][2], sh[4][2];
#pragma unroll
    for (int mtl = 0; mtl < 4; mtl++)
#pragma unroll
        for (int hh = 0; hh < 2; hh++) {
            int o = mt * 128 + warpM * 64 + mtl * 16 + g + hh * 8;
            float s_ = __ldg(g2 + o) * rsqrtf(__ldg(v2 + o) + 1e-5f);
            sc[mtl][hh] = s_;
            sh[mtl][hh] = __ldg(be2 + o) - __ldg(m2 + o) * s_;
        }
#pragma unroll
    for (int mtl = 0; mtl < 4; mtl++)
#pragma unroll
        for (int hh = 0; hh < 2; hh++) {
            int o = mt * 128 + warpM * 64 + mtl * 16 + g + hh * 8;
            float* ob = up + (((b << 8) + o) << 14);
#pragma unroll
            for (int nt = 0; nt < 4; nt++)
#pragma unroll
                for (int cc = 0; cc < 2; cc++) {
                    int n = warpN * 32 + nt * 8 + 2 * tg + cc;
                    int prr = n >> 6, qqv = n & 63;
                    int p = ((pp0 + prr) << 1) + a;
                    int qv = (qqv << 1) + qb;
                    float v = acc[mtl][nt][hh * 2 + cc];
                    ob[(p << 7) + qv] = fmaxf(fmaf(v, sc[mtl][hh], sh[mtl][hh]), 0.f);
                }
        }
}

// ---------------------------------------------------------------------------
extern "C" void kernel_launch(void* const* d_in, const int* in_sizes, int n_in,
                              void* d_out, int out_size) {
    const float* x      = (const float*)d_in[0];
    const float* w_off  = (const float*)d_in[1];
    const float* b_off  = (const float*)d_in[2];
    const float* w_dcn  = (const float*)d_in[3];
    const float* gamma1 = (const float*)d_in[4];
    const float* beta1  = (const float*)d_in[5];
    const float* mean1  = (const float*)d_in[6];
    const float* var1   = (const float*)d_in[7];
    const float* w_up   = (const float*)d_in[8];
    const float* gamma2 = (const float*)d_in[9];
    const float* beta2  = (const float*)d_in[10];
    const float* mean2  = (const float*)d_in[11];
    const float* var2   = (const float*)d_in[12];

    float* yout  = (float*)d_out;
    float* upout = yout + Y_ELEMS;

    cudaFuncSetAttribute(k_deform_mma, cudaFuncAttributeMaxDynamicSharedMemorySize, DEFORM_SMEM);

    k_prep_wA<<<4096, 256>>>(w_up);
    k_prep_wD<<<4096, 256>>>(w_dcn);
    k_prep_wO<<<512, 256>>>(w_off);
    k_off_mma<<<256, 256>>>(x, b_off);
    k_deform_mma<<<512, 256, DEFORM_SMEM>>>(x, gamma1, beta1, mean1, var1, yout);
    k_deconv_mma<<<2048, 256>>>(yout, gamma2, beta2, mean2, var2, upout);
}